// round 2
// baseline (speedup 1.0000x reference)
#include <cuda_runtime.h>
#include <math.h>

#define B_  32
#define T_  64
#define KU_ 512
#define H_  90
#define H3_ 270
#define NR  (B_*KU_)            // 16384 rows

// Persistent scratch (no runtime allocation). Ping-pong state buffers.
__device__ float g_states[2][NR*H_];
__device__ float g_gi0[H3_];    // gi for inactive rows: relu(b_agg)@Wi_rnn + bi_rnn

__device__ __forceinline__ float sigf(float x){ return 1.0f/(1.0f+__expf(-x)); }

// ---------------------------------------------------------------------------
__global__ void k_zero()
{
    float* p = (float*)g_states;
    int n = 2*NR*H_;
    for (int i = blockIdx.x*blockDim.x + threadIdx.x; i < n; i += gridDim.x*blockDim.x)
        p[i] = 0.0f;
}

// ---------------------------------------------------------------------------
__global__ void k_gi0(const float* __restrict__ bag,
                      const float* __restrict__ WiR,
                      const float* __restrict__ biR)
{
    __shared__ float inf0[H_];
    int tid = threadIdx.x;
    if (tid < H_) inf0[tid] = fmaxf(bag[tid], 0.0f);
    __syncthreads();
    if (tid < H3_) {
        float v = biR[tid];
        #pragma unroll 6
        for (int i = 0; i < H_; i++) v += inf0[i] * WiR[i*H3_ + tid];
        g_gi0[tid] = v;
    }
}

// ---------------------------------------------------------------------------
__global__ void k_copyout(float* __restrict__ out)
{
    int n = NR*H_;
    for (int i = blockIdx.x*blockDim.x + threadIdx.x; i < n; i += gridDim.x*blockDim.x)
        out[i] = g_states[0][i];
}

// ---------------------------------------------------------------------------
// One full scan step. grid = 256 CTAs (8 per batch, 64 rows each), 288 threads.
__global__ void __launch_bounds__(288, 2) k_step(int t,
    const int*   __restrict__ qs,   const int*   __restrict__ as_,
    const float* __restrict__ resp, const float* __restrict__ ce,
    const float* __restrict__ nb,   const float* __restrict__ succ,
    const float* __restrict__ WiS,  const float* __restrict__ WhS,
    const float* __restrict__ biS,  const float* __restrict__ bhS,
    const float* __restrict__ WiR,  const float* __restrict__ WhR,
    const float* __restrict__ biR,  const float* __restrict__ bhR,
    const float* __restrict__ Wsy,  const float* __restrict__ bsy,
    const float* __restrict__ Wpr,  const float* __restrict__ bpr,
    const float* __restrict__ Wag,  const float* __restrict__ bag,
    const float* __restrict__ Wo,   const float* __restrict__ bo,
    float* __restrict__ out)
{
    const float* __restrict__ Sp = g_states[t & 1];        // pre-update states
    float*       __restrict__ Sn = g_states[(t + 1) & 1];  // post-update states

    int tid   = threadIdx.x;
    int b     = blockIdx.x >> 3;
    int kbase = (blockIdx.x & 7) << 6;

    __shared__ __align__(16) float sS[8][92];   // 8 state rows (padded)
    __shared__ float sGH[8][H3_];
    __shared__ float sGI[8][H3_];
    __shared__ float sGI0[H3_];
    __shared__ float sTmpI[H3_], sTmpH[H3_];
    __shared__ float sSelf[H_], sX[H_], sNs[H_], sNsDot[H_], sProp[H_];
    __shared__ float sComb[H_], sInf[H_], sWo[H_];
    __shared__ float sNbv[8], sScv[8];
    __shared__ int   sAct[8];

    int q = qs[b*T_ + t];
    int a = as_[b*T_ + t];

    for (int j = tid; j < H3_; j += 288) sGI0[j] = g_gi0[j];
    if (tid < H_) {
        sSelf[tid] = Sp[(b*KU_ + q)*H_ + tid];
        sX[tid]    = resp[a*H_ + tid];
        sWo[tid]   = Wo[tid];
    }
    __syncthreads();

    // next_self GRU gates (two 90x270 GEMVs)
    if (tid < H3_) {
        float gi = biS[tid], gh = bhS[tid];
        #pragma unroll 6
        for (int i = 0; i < H_; i++) {
            gi += sX[i]    * WiS[i*H3_ + tid];
            gh += sSelf[i] * WhS[i*H3_ + tid];
        }
        sTmpI[tid] = gi; sTmpH[tid] = gh;
    }
    __syncthreads();
    if (tid < H_) {
        float r = sigf(sTmpI[tid]       + sTmpH[tid]);
        float z = sigf(sTmpI[H_+tid]    + sTmpH[H_+tid]);
        float g = tanhf(sTmpI[2*H_+tid] + r*sTmpH[2*H_+tid]);
        sNs[tid] = (1.0f - z)*g + z*sSelf[tid];
    }
    __syncthreads();

    // shared sync term (next_self @ W_sync[90:180]) and prop_inf (once per CTA)
    if (tid < H_) {
        float nd = 0.0f, p = bpr[tid];
        #pragma unroll 6
        for (int i = 0; i < H_; i++) nd += sNs[i] * Wsy[(H_+i)*H_ + tid];
        sNsDot[tid] = nd;
        #pragma unroll 6
        for (int i = 0; i < H_; i++) p += (sNs[i] - sSelf[i]) * Wpr[i*H_ + tid];
        #pragma unroll 6
        for (int i = 0; i < H_; i++) p += ce[q*H_ + i] * Wpr[(H_+i)*H_ + tid];
        sProp[tid] = fmaxf(p, 0.0f);
    }
    __syncthreads();

    // ---- 8 groups of 8 rows ----
    for (int g0 = 0; g0 < 8; g0++) {
        int rb = b*KU_ + kbase + g0*8;   // global row base

        // stage 8 state rows (zero-padded to 92)
        for (int idx = tid; idx < 8*92; idx += 288) {
            int r = idx / 92, i = idx - r*92;
            sS[r][i] = (i < H_) ? Sp[(rb + r)*H_ + i] : 0.0f;
        }
        if (tid < 8) {
            int k = kbase + g0*8 + tid;
            float nv = nb[q*KU_ + k], sc = succ[q*KU_ + k];
            sNbv[tid] = nv; sScv[tid] = sc;
            sAct[tid] = (k == q || nv != 0.0f || sc != 0.0f) ? 1 : 0;
        }
        __syncthreads();

        // gh[r][j] = h_r @ Wh_rnn[:,j] + bh[j]  (8-row register blocking)
        if (tid < H3_) {
            int j = tid;
            float bh = bhR[j];
            float a0=bh,a1=bh,a2=bh,a3=bh,a4=bh,a5=bh,a6=bh,a7=bh;
            const float4* v0=(const float4*)sS[0]; const float4* v1=(const float4*)sS[1];
            const float4* v2=(const float4*)sS[2]; const float4* v3=(const float4*)sS[3];
            const float4* v4=(const float4*)sS[4]; const float4* v5=(const float4*)sS[5];
            const float4* v6=(const float4*)sS[6]; const float4* v7=(const float4*)sS[7];
            #pragma unroll 2
            for (int i4 = 0; i4 < 22; i4++) {
                const float* wp = WhR + (i4*4)*H3_ + j;
                float wa = __ldg(wp), wb = __ldg(wp + H3_);
                float wc = __ldg(wp + 2*H3_), wd = __ldg(wp + 3*H3_);
                float4 s;
                s=v0[i4]; a0 += wa*s.x + wb*s.y + wc*s.z + wd*s.w;
                s=v1[i4]; a1 += wa*s.x + wb*s.y + wc*s.z + wd*s.w;
                s=v2[i4]; a2 += wa*s.x + wb*s.y + wc*s.z + wd*s.w;
                s=v3[i4]; a3 += wa*s.x + wb*s.y + wc*s.z + wd*s.w;
                s=v4[i4]; a4 += wa*s.x + wb*s.y + wc*s.z + wd*s.w;
                s=v5[i4]; a5 += wa*s.x + wb*s.y + wc*s.z + wd*s.w;
                s=v6[i4]; a6 += wa*s.x + wb*s.y + wc*s.z + wd*s.w;
                s=v7[i4]; a7 += wa*s.x + wb*s.y + wc*s.z + wd*s.w;
            }
            #pragma unroll
            for (int i = 88; i < H_; i++) {
                float w = __ldg(WhR + i*H3_ + j);
                a0 += w*sS[0][i]; a1 += w*sS[1][i]; a2 += w*sS[2][i]; a3 += w*sS[3][i];
                a4 += w*sS[4][i]; a5 += w*sS[5][i]; a6 += w*sS[6][i]; a7 += w*sS[7][i];
            }
            sGH[0][j]=a0; sGH[1][j]=a1; sGH[2][j]=a2; sGH[3][j]=a3;
            sGH[4][j]=a4; sGH[5][j]=a5; sGH[6][j]=a6; sGH[7][j]=a7;
        }
        __syncthreads();

        // active rows (~4%): sync/reflec -> comb -> inf -> gi (block-uniform branches)
        for (int r = 0; r < 8; r++) {
            if (!sAct[r]) continue;
            int k = kbase + g0*8 + r;
            float nv = sNbv[r], sc = sScv[r];
            if (tid < H_) {
                float sv = 0.0f;
                if (nv != 0.0f) {
                    float v = bsy[tid] + sNsDot[tid];
                    #pragma unroll 6
                    for (int i = 0; i < H_; i++) v += sS[r][i] * Wsy[i*H_ + tid];
                    #pragma unroll 6
                    for (int i = 0; i < H_; i++) v += ce[k*H_ + i] * Wsy[(2*H_+i)*H_ + tid];
                    sv = nv * fmaxf(v, 0.0f);
                }
                if (k == q) {  // reflec: deterministic scan over nb-masked rows
                    const float* nrow = nb + q*KU_;
                    for (int k2 = 0; k2 < KU_; k2++) {
                        float nv2 = nrow[k2];
                        if (nv2 != 0.0f) {
                            float v = bsy[tid] + sNsDot[tid];
                            const float* hr = Sp + (b*KU_ + k2)*H_;
                            #pragma unroll 6
                            for (int i = 0; i < H_; i++) v += hr[i] * Wsy[i*H_ + tid];
                            #pragma unroll 6
                            for (int i = 0; i < H_; i++) v += ce[k2*H_ + i] * Wsy[(2*H_+i)*H_ + tid];
                            sv += nv2 * fmaxf(v, 0.0f);
                        }
                    }
                }
                sComb[tid] = 0.5f*sv + 0.5f*sc*sProp[tid];
            }
            __syncthreads();
            if (tid < H_) {
                float v = bag[tid];
                #pragma unroll 6
                for (int i = 0; i < H_; i++) v += sComb[i] * Wag[i*H_ + tid];
                sInf[tid] = fmaxf(v, 0.0f);
            }
            __syncthreads();
            if (tid < H3_) {
                float v = biR[tid];
                #pragma unroll 6
                for (int i = 0; i < H_; i++) v += sInf[i] * WiR[i*H3_ + tid];
                sGI[r][tid] = v;
            }
            __syncthreads();
        }

        // GRU gates + state update (write Sn, keep new h in sS for the out dot)
        for (int w = tid; w < 8*H_; w += 288) {
            int r = w / H_, jj = w - r*H_;
            const float* gi = sAct[r] ? sGI[r] : sGI0;
            float gr = sigf(gi[jj]       + sGH[r][jj]);
            float gz = sigf(gi[H_+jj]    + sGH[r][H_+jj]);
            float gg = tanhf(gi[2*H_+jj] + gr*sGH[r][2*H_+jj]);
            float nh = (1.0f - gz)*gg + gz*sS[r][jj];
            Sn[(rb + r)*H_ + jj] = nh;
            sS[r][jj] = nh;
        }
        __syncthreads();

        // out[t, b, k] = sigmoid(new_h @ W_out + b_out)  (one warp per row)
        if (tid < 256) {
            int r = tid >> 5, lane = tid & 31;
            float p = 0.0f;
            for (int i = lane; i < H_; i += 32) p += sS[r][i] * sWo[i];
            #pragma unroll
            for (int o = 16; o > 0; o >>= 1) p += __shfl_down_sync(0xffffffffu, p, o);
            if (lane == 0) out[(size_t)t*NR + rb + r] = sigf(p + bo[0]);
        }
        __syncthreads();
    }
}

// ---------------------------------------------------------------------------
extern "C" void kernel_launch(void* const* d_in, const int* in_sizes, int n_in,
                              void* d_out, int out_size)
{
    const int*   qs   = (const int*)  d_in[0];
    const int*   as_  = (const int*)  d_in[1];
    const float* resp = (const float*)d_in[2];
    const float* ce   = (const float*)d_in[3];
    const float* nb   = (const float*)d_in[4];
    const float* succ = (const float*)d_in[5];
    const float* WiS  = (const float*)d_in[6];
    const float* WhS  = (const float*)d_in[7];
    const float* biS  = (const float*)d_in[8];
    const float* bhS  = (const float*)d_in[9];
    const float* WiR  = (const float*)d_in[10];
    const float* WhR  = (const float*)d_in[11];
    const float* biR  = (const float*)d_in[12];
    const float* bhR  = (const float*)d_in[13];
    const float* Wsy  = (const float*)d_in[14];
    const float* bsy  = (const float*)d_in[15];
    const float* Wpr  = (const float*)d_in[16];
    const float* bpr  = (const float*)d_in[17];
    const float* Wag  = (const float*)d_in[18];
    const float* bag  = (const float*)d_in[19];
    const float* Wo   = (const float*)d_in[20];
    const float* bo   = (const float*)d_in[21];
    float* out = (float*)d_out;

    k_zero<<<256, 256>>>();
    k_gi0<<<1, 288>>>(bag, WiR, biR);
    for (int t = 0; t < T_; t++) {
        k_step<<<256, 288>>>(t, qs, as_, resp, ce, nb, succ,
                             WiS, WhS, biS, bhS, WiR, WhR, biR, bhR,
                             Wsy, bsy, Wpr, bpr, Wag, bag, Wo, bo, out);
    }
    // T=64 even -> final states land in buffer 0; append to output.
    k_copyout<<<512, 256>>>(out + (size_t)T_*NR);
}

// round 8
// speedup vs baseline: 1.9185x; 1.9185x over previous
#include <cuda_runtime.h>
#include <math.h>

#define B_  32
#define T_  64
#define KU_ 512
#define H_  90
#define H2_ 45               // H/2
#define H3_ 270
#define NR  (B_*KU_)         // 16384
#define RPC 16               // rows per CTA (main)
#define NCTA (NR/RPC)        // 1024

// Persistent scratch (zero runtime allocation). Ping-pong states.
__device__ float g_states[2][NR*H_];
__device__ float g_gi0[H3_];       // gi for inactive rows
__device__ float g_sync[NR*H_];    // sync rows (valid only where nb!=0 this step)
__device__ float g_prop[B_*H_];    // prop_inf per batch
__device__ float g_rflp[B_][4][H_];// partial reflec sums per k-slice

__device__ __forceinline__ float sigf(float x){ return 1.0f/(1.0f+__expf(-x)); }

__device__ __forceinline__ unsigned long long pack2(float a, float b){
    unsigned long long r;
    asm("mov.b64 %0, {%1, %2};" : "=l"(r) : "f"(a), "f"(b));
    return r;
}
__device__ __forceinline__ void unpack2(unsigned long long v, float& a, float& b){
    asm("mov.b64 {%0, %1}, %2;" : "=f"(a), "=f"(b) : "l"(v));
}
// Packed dual fp32 FMA (sm_100+): acc.lo += a.lo*b.lo; acc.hi += a.hi*b.hi
__device__ __forceinline__ void ffma2(unsigned long long& acc,
                                      unsigned long long a, unsigned long long b){
    asm("fma.rn.f32x2 %0, %1, %2, %0;" : "+l"(acc) : "l"(a), "l"(b));
}

// ---------------------------------------------------------------------------
__global__ void k_zero()
{
    float* p = (float*)g_states;
    int n = 2*NR*H_;
    for (int i = blockIdx.x*blockDim.x + threadIdx.x; i < n; i += gridDim.x*blockDim.x)
        p[i] = 0.0f;
}

__global__ void k_gi0(const float* __restrict__ bag,
                      const float* __restrict__ WiR,
                      const float* __restrict__ biR)
{
    __shared__ float inf0[H_];
    int tid = threadIdx.x;
    if (tid < H_) inf0[tid] = fmaxf(bag[tid], 0.0f);
    __syncthreads();
    if (tid < H3_) {
        float v = biR[tid];
        #pragma unroll 6
        for (int i = 0; i < H_; i++) v += inf0[i] * WiR[i*H3_ + tid];
        g_gi0[tid] = v;
    }
}

__global__ void k_copyout(float* __restrict__ out)
{
    int n = NR*H_;
    for (int i = blockIdx.x*blockDim.x + threadIdx.x; i < n; i += gridDim.x*blockDim.x)
        out[i] = g_states[0][i];
}

// ---------------------------------------------------------------------------
// Prep: next_self GRU, nsdot, prop, nb-masked sync rows + partial reflec.
// grid = (32 batches, 4 k-slices of 128), block 288.
__global__ void __launch_bounds__(288) k_prep(int t,
    const int*   __restrict__ qs,   const int*   __restrict__ as_,
    const float* __restrict__ resp, const float* __restrict__ ce,
    const float* __restrict__ nb,
    const float* __restrict__ WiS,  const float* __restrict__ WhS,
    const float* __restrict__ biS,  const float* __restrict__ bhS,
    const float* __restrict__ Wsy,  const float* __restrict__ bsy,
    const float* __restrict__ Wpr,  const float* __restrict__ bpr)
{
    const float* __restrict__ Sp = g_states[t & 1];
    int b = blockIdx.x, sl = blockIdx.y, tid = threadIdx.x;

    __shared__ float sSelf[H_], sX[H_], sGi[H3_], sGh[H3_], sNs[H_], sNsDot[H_];
    __shared__ float sNb[128];

    int q = qs[b*T_ + t];
    int a = as_[b*T_ + t];
    if (tid < H_) { sSelf[tid] = Sp[(b*KU_ + q)*H_ + tid]; sX[tid] = resp[a*H_ + tid]; }
    if (tid < 128) sNb[tid] = nb[q*KU_ + sl*128 + tid];
    __syncthreads();

    if (tid < H3_) {
        float gi = biS[tid], gh = bhS[tid];
        #pragma unroll 6
        for (int i = 0; i < H_; i++) {
            gi += sX[i]    * WiS[i*H3_ + tid];
            gh += sSelf[i] * WhS[i*H3_ + tid];
        }
        sGi[tid] = gi; sGh[tid] = gh;
    }
    __syncthreads();
    if (tid < H_) {
        float r = sigf(sGi[tid]       + sGh[tid]);
        float z = sigf(sGi[H_+tid]    + sGh[H_+tid]);
        float g = tanhf(sGi[2*H_+tid] + r*sGh[2*H_+tid]);
        sNs[tid] = (1.0f - z)*g + z*sSelf[tid];
    }
    __syncthreads();
    if (tid < H_) {
        float nd = 0.0f;
        #pragma unroll 6
        for (int i = 0; i < H_; i++) nd += sNs[i] * Wsy[(H_+i)*H_ + tid];
        sNsDot[tid] = nd;
        if (sl == 0) {
            float p = bpr[tid];
            #pragma unroll 6
            for (int i = 0; i < H_; i++) p += (sNs[i] - sSelf[i]) * Wpr[i*H_ + tid];
            #pragma unroll 6
            for (int i = 0; i < H_; i++) p += ce[q*H_ + i] * Wpr[(H_+i)*H_ + tid];
            g_prop[b*H_ + tid] = fmaxf(p, 0.0f);
        }
    }
    __syncthreads();

    float rfl = 0.0f;
    for (int kk = 0; kk < 128; kk++) {
        float nv = sNb[kk];                 // uniform across block
        if (nv != 0.0f) {
            int k = sl*128 + kk;
            if (tid < H_) {
                float v = bsy[tid] + sNsDot[tid];
                const float* hr = Sp + (b*KU_ + k)*H_;
                const float* cr = ce + k*H_;
                #pragma unroll 6
                for (int i = 0; i < H_; i++) v += hr[i] * Wsy[i*H_ + tid];
                #pragma unroll 6
                for (int i = 0; i < H_; i++) v += cr[i] * Wsy[(2*H_+i)*H_ + tid];
                float val = nv * fmaxf(v, 0.0f);
                g_sync[(b*KU_ + k)*H_ + tid] = val;
                rfl += val;
            }
        }
    }
    if (tid < H_) g_rflp[b][sl][tid] = rfl;
}

// ---------------------------------------------------------------------------
// Main: recurrent gh GEMM (f32x2 packed, 16 rows/CTA) + gates + out.
// grid = 1024 (32 batches x 32 tiles of 16 rows), block 288, 4 CTAs/SM.
__global__ void __launch_bounds__(288, 4) k_main(int t,
    const int*   __restrict__ qs,
    const float* __restrict__ nb,   const float* __restrict__ succ,
    const float* __restrict__ WiR,  const float* __restrict__ WhR,
    const float* __restrict__ biR,  const float* __restrict__ bhR,
    const float* __restrict__ Wag,  const float* __restrict__ bag,
    const float* __restrict__ Wo,   const float* __restrict__ bo,
    float* __restrict__ out)
{
    const float* __restrict__ Sp = g_states[t & 1];
    float*       __restrict__ Sn = g_states[(t + 1) & 1];

    int tid   = threadIdx.x;
    int b     = blockIdx.x >> 5;
    int kbase = (blockIdx.x & 31) * RPC;
    int rb    = b*KU_ + kbase;

    __shared__ __align__(16) float4 sP[H2_][8];  // packed: rows(2p,2p+1) x cols(2i,2i+1)
    __shared__ float sGH[RPC][H3_];
    __shared__ float sGI[RPC][H3_];
    __shared__ float sGI0[H3_];
    __shared__ float sProp[H_], sRef[H_], sWo[H_], sComb[H_], sInf[H_];
    __shared__ float sNv[RPC], sSc[RPC];
    __shared__ int   sAct[RPC];

    int q = qs[b*T_ + t];

    for (int j = tid; j < H3_; j += 288) sGI0[j] = g_gi0[j];
    if (tid < H_) {
        sProp[tid] = g_prop[b*H_ + tid];
        sRef[tid]  = g_rflp[b][0][tid] + g_rflp[b][1][tid]
                   + g_rflp[b][2][tid] + g_rflp[b][3][tid];
        sWo[tid]   = Wo[tid];
    }
    if (tid < RPC) {
        int k = kbase + tid;
        float nv = nb[q*KU_ + k], sc = succ[q*KU_ + k];
        sNv[tid] = nv; sSc[tid] = sc;
        sAct[tid] = (k == q || nv != 0.0f || sc != 0.0f) ? 1 : 0;
    }
    // stage 16 state rows as row-pair/col-pair packs
    for (int idx = tid; idx < H2_*8; idx += 288) {
        int i2 = idx >> 3, p = idx & 7;
        const float* ra = Sp + (rb + 2*p    )*H_ + 2*i2;
        const float* rbp= Sp + (rb + 2*p + 1)*H_ + 2*i2;
        float2 va = *(const float2*)ra;
        float2 vb = *(const float2*)rbp;
        sP[i2][p] = make_float4(va.x, vb.x, va.y, vb.y);
    }
    __syncthreads();

    // gh[r][j] = h_r @ WhR[:,j] + bh[j]; thread j owns a column, 8 f32x2 accs = 16 rows
    if (tid < H3_) {
        int j = tid;
        float bh = bhR[j];
        unsigned long long acc[8];
        unsigned long long bh2 = pack2(bh, bh);
        #pragma unroll
        for (int p = 0; p < 8; p++) acc[p] = bh2;
        #pragma unroll 5
        for (int i2 = 0; i2 < H2_; i2++) {
            float wa = __ldg(WhR + (2*i2    )*H3_ + j);
            float wb = __ldg(WhR + (2*i2 + 1)*H3_ + j);
            unsigned long long w2a = pack2(wa, wa);
            unsigned long long w2b = pack2(wb, wb);
            #pragma unroll
            for (int p = 0; p < 8; p++) {
                ulonglong2 uu = *(const ulonglong2*)&sP[i2][p];
                ffma2(acc[p], w2a, uu.x);
                ffma2(acc[p], w2b, uu.y);
            }
        }
        #pragma unroll
        for (int p = 0; p < 8; p++) {
            float lo, hi; unpack2(acc[p], lo, hi);
            sGH[2*p][j] = lo; sGH[2*p+1][j] = hi;
        }
    }
    __syncthreads();

    // active rows (~4%): comb -> inf -> gi (block-uniform branches)
    for (int r = 0; r < RPC; r++) {
        if (!sAct[r]) continue;
        int k = kbase + r;
        float nv = sNv[r], sc = sSc[r];
        if (tid < H_) {
            float sv = (nv != 0.0f) ? g_sync[(rb + r)*H_ + tid] : 0.0f;
            if (k == q) sv += sRef[tid];
            sComb[tid] = 0.5f*sv + 0.5f*sc*sProp[tid];
        }
        __syncthreads();
        if (tid < H_) {
            float v = bag[tid];
            #pragma unroll 6
            for (int i = 0; i < H_; i++) v += sComb[i] * Wag[i*H_ + tid];
            sInf[tid] = fmaxf(v, 0.0f);
        }
        __syncthreads();
        if (tid < H3_) {
            float v = biR[tid];
            #pragma unroll 6
            for (int i = 0; i < H_; i++) v += sInf[i] * WiR[i*H3_ + tid];
            sGI[r][tid] = v;
        }
        __syncthreads();
    }

    // gates + state update; new h into sNH (aliases sP, dead after GEMM)
    float* sNH = (float*)sP;   // RPC*H_ = 1440 floats = sizeof(sP)
    for (int w = tid; w < RPC*H_; w += 288) {
        int r = w / H_, jj = w - r*H_;
        const float* gi = sAct[r] ? sGI[r] : sGI0;
        float gr = sigf(gi[jj]       + sGH[r][jj]);
        float gz = sigf(gi[H_+jj]    + sGH[r][H_+jj]);
        float gg = tanhf(gi[2*H_+jj] + gr*sGH[r][2*H_+jj]);
        float nh = (1.0f - gz)*gg + gz*Sp[(rb + r)*H_ + jj];
        Sn[(rb + r)*H_ + jj] = nh;
        sNH[w] = nh;
    }
    __syncthreads();

    // out[t,b,k] = sigmoid(new_h . W_out + b_out); warp per row, 2 passes
    {
        int lane = tid & 31;
        for (int r = tid >> 5; r < RPC; r += 9) {
            float p = 0.0f;
            for (int i = lane; i < H_; i += 32) p += sNH[r*H_ + i] * sWo[i];
            #pragma unroll
            for (int o = 16; o > 0; o >>= 1) p += __shfl_down_sync(0xffffffffu, p, o);
            if (lane == 0) out[(size_t)t*NR + rb + r] = sigf(p + bo[0]);
        }
    }
}

// ---------------------------------------------------------------------------
extern "C" void kernel_launch(void* const* d_in, const int* in_sizes, int n_in,
                              void* d_out, int out_size)
{
    const int*   qs   = (const int*)  d_in[0];
    const int*   as_  = (const int*)  d_in[1];
    const float* resp = (const float*)d_in[2];
    const float* ce   = (const float*)d_in[3];
    const float* nb   = (const float*)d_in[4];
    const float* succ = (const float*)d_in[5];
    const float* WiS  = (const float*)d_in[6];
    const float* WhS  = (const float*)d_in[7];
    const float* biS  = (const float*)d_in[8];
    const float* bhS  = (const float*)d_in[9];
    const float* WiR  = (const float*)d_in[10];
    const float* WhR  = (const float*)d_in[11];
    const float* biR  = (const float*)d_in[12];
    const float* bhR  = (const float*)d_in[13];
    const float* Wsy  = (const float*)d_in[14];
    const float* bsy  = (const float*)d_in[15];
    const float* Wpr  = (const float*)d_in[16];
    const float* bpr  = (const float*)d_in[17];
    const float* Wag  = (const float*)d_in[18];
    const float* bag  = (const float*)d_in[19];
    const float* Wo   = (const float*)d_in[20];
    const float* bo   = (const float*)d_in[21];
    float* out = (float*)d_out;

    k_zero<<<256, 256>>>();
    k_gi0<<<1, 288>>>(bag, WiR, biR);
    for (int t = 0; t < T_; t++) {
        k_prep<<<dim3(B_, 4), 288>>>(t, qs, as_, resp, ce, nb,
                                     WiS, WhS, biS, bhS, Wsy, bsy, Wpr, bpr);
        k_main<<<NCTA, 288>>>(t, qs, nb, succ, WiR, WhR, biR, bhR,
                              Wag, bag, Wo, bo, out);
    }
    // T=64 even -> final states in buffer 0; append after outputs.
    k_copyout<<<512, 256>>>(out + (size_t)T_*NR);
}

// round 12
// speedup vs baseline: 2.3498x; 1.2248x over previous
#include <cuda_runtime.h>
#include <math.h>

#define B_  32
#define T_  64
#define KU_ 512
#define H_  90
#define H2_ 45               // H/2
#define H3_ 270
#define NR  (B_*KU_)         // 16384
#define RPC 16               // rows per CTA (main)
#define NCTA (NR/RPC)        // 1024
#define SL_ 16               // prep slices per batch
#define KS_ (KU_/SL_)        // 32 k's per slice

// Persistent scratch (zero runtime allocation). Ping-pong states.
__device__ float g_states[2][NR*H_];
__device__ float g_gi0[H3_];        // gi for inactive rows
__device__ float g_sync[NR*H_];     // sync rows (valid only where nb!=0 this step)
__device__ float g_prop[B_*H_];     // prop_inf per batch
__device__ float g_rflp[B_][SL_][H_]; // partial reflec sums per k-slice
__device__ float g_gia[(size_t)NR*H3_]; // gi for active rows (written by prep2)

__device__ __forceinline__ float sigf(float x){ return 1.0f/(1.0f+__expf(-x)); }
__device__ __forceinline__ float tanhfast(float x){ return 2.0f*sigf(2.0f*x) - 1.0f; }

__device__ __forceinline__ unsigned long long pack2(float a, float b){
    unsigned long long r;
    asm("mov.b64 %0, {%1, %2};" : "=l"(r) : "f"(a), "f"(b));
    return r;
}
__device__ __forceinline__ void unpack2(unsigned long long v, float& a, float& b){
    asm("mov.b64 {%0, %1}, %2;" : "=f"(a), "=f"(b) : "l"(v));
}
// Packed dual fp32 FMA (sm_100+): acc.lo += a.lo*b.lo; acc.hi += a.hi*b.hi
__device__ __forceinline__ void ffma2(unsigned long long& acc,
                                      unsigned long long a, unsigned long long b){
    asm("fma.rn.f32x2 %0, %1, %2, %0;" : "+l"(acc) : "l"(a), "l"(b));
}

// ---------------------------------------------------------------------------
__global__ void k_zero()
{
    float* p = (float*)g_states;
    int n = 2*NR*H_;
    for (int i = blockIdx.x*blockDim.x + threadIdx.x; i < n; i += gridDim.x*blockDim.x)
        p[i] = 0.0f;
}

__global__ void k_gi0(const float* __restrict__ bag,
                      const float* __restrict__ WiR,
                      const float* __restrict__ biR)
{
    __shared__ float inf0[H_];
    int tid = threadIdx.x;
    if (tid < H_) inf0[tid] = fmaxf(bag[tid], 0.0f);
    __syncthreads();
    if (tid < H3_) {
        float v = biR[tid];
        #pragma unroll 6
        for (int i = 0; i < H_; i++) v += inf0[i] * WiR[i*H3_ + tid];
        g_gi0[tid] = v;
    }
}

__global__ void k_copyout(float* __restrict__ out)
{
    int n = NR*H_;
    for (int i = blockIdx.x*blockDim.x + threadIdx.x; i < n; i += gridDim.x*blockDim.x)
        out[i] = g_states[0][i];
}

// ---------------------------------------------------------------------------
// Prep1: next_self GRU, nsdot, prop, nb-masked sync rows + partial reflec.
// grid = (32 batches, 16 k-slices of 32), block 288.
__global__ void __launch_bounds__(288) k_prep1(int t,
    const int*   __restrict__ qs,   const int*   __restrict__ as_,
    const float* __restrict__ resp, const float* __restrict__ ce,
    const float* __restrict__ nb,
    const float* __restrict__ WiS,  const float* __restrict__ WhS,
    const float* __restrict__ biS,  const float* __restrict__ bhS,
    const float* __restrict__ Wsy,  const float* __restrict__ bsy,
    const float* __restrict__ Wpr,  const float* __restrict__ bpr)
{
    const float* __restrict__ Sp = g_states[t & 1];
    int b = blockIdx.x, sl = blockIdx.y, tid = threadIdx.x;

    __shared__ float sSelf[H_], sX[H_], sGi[H3_], sGh[H3_], sNs[H_], sNsDot[H_];
    __shared__ float sNb[KS_];

    int q = qs[b*T_ + t];
    int a = as_[b*T_ + t];
    if (tid < H_) { sSelf[tid] = Sp[(b*KU_ + q)*H_ + tid]; sX[tid] = resp[a*H_ + tid]; }
    if (tid < KS_) sNb[tid] = nb[q*KU_ + sl*KS_ + tid];
    __syncthreads();

    if (tid < H3_) {
        float gi = biS[tid], gh = bhS[tid];
        #pragma unroll 6
        for (int i = 0; i < H_; i++) {
            gi += sX[i]    * WiS[i*H3_ + tid];
            gh += sSelf[i] * WhS[i*H3_ + tid];
        }
        sGi[tid] = gi; sGh[tid] = gh;
    }
    __syncthreads();
    if (tid < H_) {
        float r = sigf(sGi[tid]       + sGh[tid]);
        float z = sigf(sGi[H_+tid]    + sGh[H_+tid]);
        float g = tanhfast(sGi[2*H_+tid] + r*sGh[2*H_+tid]);
        sNs[tid] = (1.0f - z)*g + z*sSelf[tid];
    }
    __syncthreads();
    if (tid < H_) {
        float nd = 0.0f;
        #pragma unroll 6
        for (int i = 0; i < H_; i++) nd += sNs[i] * Wsy[(H_+i)*H_ + tid];
        sNsDot[tid] = nd;
        if (sl == 0) {
            float p = bpr[tid];
            #pragma unroll 6
            for (int i = 0; i < H_; i++) p += (sNs[i] - sSelf[i]) * Wpr[i*H_ + tid];
            #pragma unroll 6
            for (int i = 0; i < H_; i++) p += ce[q*H_ + i] * Wpr[(H_+i)*H_ + tid];
            g_prop[b*H_ + tid] = fmaxf(p, 0.0f);
        }
    }
    __syncthreads();

    float rfl = 0.0f;
    for (int kk = 0; kk < KS_; kk++) {
        float nv = sNb[kk];                 // uniform across block
        if (nv != 0.0f) {
            int k = sl*KS_ + kk;
            if (tid < H_) {
                float v = bsy[tid] + sNsDot[tid];
                const float* hr = Sp + (b*KU_ + k)*H_;
                const float* cr = ce + k*H_;
                #pragma unroll 6
                for (int i = 0; i < H_; i++) v += hr[i] * Wsy[i*H_ + tid];
                #pragma unroll 6
                for (int i = 0; i < H_; i++) v += cr[i] * Wsy[(2*H_+i)*H_ + tid];
                float val = nv * fmaxf(v, 0.0f);
                g_sync[(b*KU_ + k)*H_ + tid] = val;
                rfl += val;
            }
        }
    }
    if (tid < H_) g_rflp[b][sl][tid] = rfl;
}

// ---------------------------------------------------------------------------
// Prep2: gi for active rows -> g_gia. grid = (32, 16), block 288.
__global__ void __launch_bounds__(288) k_prep2(int t,
    const int*   __restrict__ qs,
    const float* __restrict__ nb,  const float* __restrict__ succ,
    const float* __restrict__ Wag, const float* __restrict__ bag,
    const float* __restrict__ WiR, const float* __restrict__ biR)
{
    int b = blockIdx.x, sl = blockIdx.y, tid = threadIdx.x;
    __shared__ float sProp[H_], sRef[H_], sComb[H_], sInf[H_];
    __shared__ float sNv[KS_], sSc[KS_];

    int q = qs[b*T_ + t];
    if (tid < H_) {
        sProp[tid] = g_prop[b*H_ + tid];
        float rf = 0.0f;
        #pragma unroll
        for (int s2 = 0; s2 < SL_; s2++) rf += g_rflp[b][s2][tid];
        sRef[tid] = rf;
    }
    if (tid < KS_) {
        int k = sl*KS_ + tid;
        sNv[tid] = nb[q*KU_ + k];
        sSc[tid] = succ[q*KU_ + k];
    }
    __syncthreads();

    for (int kk = 0; kk < KS_; kk++) {
        int k = sl*KS_ + kk;
        float nv = sNv[kk], sc = sSc[kk];
        bool act = (k == q) || (nv != 0.0f) || (sc != 0.0f);   // block-uniform
        if (!act) continue;
        int row = b*KU_ + k;
        if (tid < H_) {
            float sv = (nv != 0.0f) ? g_sync[row*H_ + tid] : 0.0f;
            if (k == q) sv += sRef[tid];
            sComb[tid] = 0.5f*sv + 0.5f*sc*sProp[tid];
        }
        __syncthreads();
        if (tid < H_) {
            float v = bag[tid];
            #pragma unroll 6
            for (int i = 0; i < H_; i++) v += sComb[i] * Wag[i*H_ + tid];
            sInf[tid] = fmaxf(v, 0.0f);
        }
        __syncthreads();
        if (tid < H3_) {
            float v = biR[tid];
            #pragma unroll 6
            for (int i = 0; i < H_; i++) v += sInf[i] * WiR[i*H3_ + tid];
            g_gia[(size_t)row*H3_ + tid] = v;
        }
        __syncthreads();
    }
}

// ---------------------------------------------------------------------------
// Main: recurrent gh GEMM (f32x2 packed, 16 rows/CTA) + gates + out.
// grid = 1024, block 288, 4 CTAs/SM (reg-capped).
__global__ void __launch_bounds__(288, 4) k_main(int t,
    const int*   __restrict__ qs,
    const float* __restrict__ nb,   const float* __restrict__ succ,
    const float* __restrict__ WhR,  const float* __restrict__ bhR,
    const float* __restrict__ Wo,   const float* __restrict__ bo,
    float* __restrict__ out)
{
    const float* __restrict__ Sp = g_states[t & 1];
    float*       __restrict__ Sn = g_states[(t + 1) & 1];

    int tid   = threadIdx.x;
    int b     = blockIdx.x >> 5;
    int kbase = (blockIdx.x & 31) * RPC;
    int rb    = b*KU_ + kbase;

    __shared__ __align__(16) float4 sP[H2_][8];  // packed: rows(2p,2p+1) x cols(2i,2i+1)
    __shared__ float sGH[RPC][H3_];
    __shared__ float sWo[H_];
    __shared__ float sNv[RPC], sSc[RPC];
    __shared__ int   sAct[RPC];

    int q = qs[b*T_ + t];

    if (tid < H_) sWo[tid] = Wo[tid];
    if (tid < RPC) {
        int k = kbase + tid;
        float nv = nb[q*KU_ + k], sc = succ[q*KU_ + k];
        sNv[tid] = nv; sSc[tid] = sc;
        sAct[tid] = (k == q || nv != 0.0f || sc != 0.0f) ? 1 : 0;
    }
    // stage 16 state rows as row-pair/col-pair packs
    for (int idx = tid; idx < H2_*8; idx += 288) {
        int i2 = idx >> 3, p = idx & 7;
        const float* ra = Sp + (rb + 2*p    )*H_ + 2*i2;
        const float* rbp= Sp + (rb + 2*p + 1)*H_ + 2*i2;
        float2 va = *(const float2*)ra;
        float2 vb = *(const float2*)rbp;
        sP[i2][p] = make_float4(va.x, vb.x, va.y, vb.y);
    }
    __syncthreads();

    // gh[r][j] = h_r @ WhR[:,j] + bh[j]; thread j owns a column, 8 f32x2 accs = 16 rows
    if (tid < H3_) {
        int j = tid;
        float bh = bhR[j];
        unsigned long long acc[8];
        unsigned long long bh2 = pack2(bh, bh);
        #pragma unroll
        for (int p = 0; p < 8; p++) acc[p] = bh2;
        #pragma unroll 5
        for (int i2 = 0; i2 < H2_; i2++) {
            float wa = __ldg(WhR + (2*i2    )*H3_ + j);
            float wb = __ldg(WhR + (2*i2 + 1)*H3_ + j);
            unsigned long long w2a = pack2(wa, wa);
            unsigned long long w2b = pack2(wb, wb);
            #pragma unroll
            for (int p = 0; p < 8; p++) {
                ulonglong2 uu = *(const ulonglong2*)&sP[i2][p];
                ffma2(acc[p], w2a, uu.x);
                ffma2(acc[p], w2b, uu.y);
            }
        }
        #pragma unroll
        for (int p = 0; p < 8; p++) {
            float lo, hi; unpack2(acc[p], lo, hi);
            sGH[2*p][j] = lo; sGH[2*p+1][j] = hi;
        }
    }
    __syncthreads();

    // gates + state update; gi from g_gia (active) or g_gi0 (inactive)
    float* sNH = (float*)sP;   // RPC*H_ = 1440 floats = sizeof(sP); sP dead after GEMM
    for (int w = tid; w < RPC*H_; w += 288) {
        int r = w / H_, jj = w - r*H_;
        int row = rb + r;
        const float* gi = sAct[r] ? (g_gia + (size_t)row*H3_) : g_gi0;
        float g0 = __ldg(gi + jj);
        float g1 = __ldg(gi + H_ + jj);
        float g2 = __ldg(gi + 2*H_ + jj);
        float gr = sigf(g0 + sGH[r][jj]);
        float gz = sigf(g1 + sGH[r][H_+jj]);
        float gg = tanhfast(g2 + gr*sGH[r][2*H_+jj]);
        float nh = (1.0f - gz)*gg + gz*Sp[row*H_ + jj];   // Sp line L1-hot from staging
        Sn[row*H_ + jj] = nh;
        sNH[w] = nh;
    }
    __syncthreads();

    // out[t,b,k] = sigmoid(new_h . W_out + b_out); warp per row, 2 passes
    {
        int lane = tid & 31;
        for (int r = tid >> 5; r < RPC; r += 9) {
            float p = 0.0f;
            for (int i = lane; i < H_; i += 32) p += sNH[r*H_ + i] * sWo[i];
            #pragma unroll
            for (int o = 16; o > 0; o >>= 1) p += __shfl_down_sync(0xffffffffu, p, o);
            if (lane == 0) out[(size_t)t*NR + rb + r] = sigf(p + bo[0]);
        }
    }
}

// ---------------------------------------------------------------------------
extern "C" void kernel_launch(void* const* d_in, const int* in_sizes, int n_in,
                              void* d_out, int out_size)
{
    const int*   qs   = (const int*)  d_in[0];
    const int*   as_  = (const int*)  d_in[1];
    const float* resp = (const float*)d_in[2];
    const float* ce   = (const float*)d_in[3];
    const float* nb   = (const float*)d_in[4];
    const float* succ = (const float*)d_in[5];
    const float* WiS  = (const float*)d_in[6];
    const float* WhS  = (const float*)d_in[7];
    const float* biS  = (const float*)d_in[8];
    const float* bhS  = (const float*)d_in[9];
    const float* WiR  = (const float*)d_in[10];
    const float* WhR  = (const float*)d_in[11];
    const float* biR  = (const float*)d_in[12];
    const float* bhR  = (const float*)d_in[13];
    const float* Wsy  = (const float*)d_in[14];
    const float* bsy  = (const float*)d_in[15];
    const float* Wpr  = (const float*)d_in[16];
    const float* bpr  = (const float*)d_in[17];
    const float* Wag  = (const float*)d_in[18];
    const float* bag  = (const float*)d_in[19];
    const float* Wo   = (const float*)d_in[20];
    const float* bo   = (const float*)d_in[21];
    float* out = (float*)d_out;

    k_zero<<<256, 256>>>();
    k_gi0<<<1, 288>>>(bag, WiR, biR);
    for (int t = 0; t < T_; t++) {
        k_prep1<<<dim3(B_, SL_), 288>>>(t, qs, as_, resp, ce, nb,
                                        WiS, WhS, biS, bhS, Wsy, bsy, Wpr, bpr);
        k_prep2<<<dim3(B_, SL_), 288>>>(t, qs, nb, succ, Wag, bag, WiR, biR);
        k_main<<<NCTA, 288>>>(t, qs, nb, succ, WhR, bhR, Wo, bo, out);
    }
    // T=64 even -> final states in buffer 0; append after outputs.
    k_copyout<<<512, 256>>>(out + (size_t)T_*NR);
}